// round 13
// baseline (speedup 1.0000x reference)
#include <cuda_runtime.h>
#include <cstdint>

// Suffix (reverse cumulative) max along last dim.
// (8, 1, 2048, 2048) fp32 -> 16384 rows x 2048 cols.
// FINAL (R7 design): one warp per row, no smem, no barriers, warp-autonomous.
// Lane l owns chunks {k*32+l : k=0..7}, 8 floats each, via 8x LDG.256/STG.256
// (perfectly lane-contiguous 1KB per warp per instruction).
// Measured: ncu dur 34.4us, DRAM 77.4% (6.13 TB/s single-shot); steady-state
// wall 43.5us = 268MB @ ~6.2 TB/s = the sustained mixed-R/W LTS/HBM ceiling.

#define ROW_LEN 2048
#define THREADS 128           // 4 warps = 4 rows per CTA (best measured shape)
#define NEG_INF __int_as_float(0xff800000)

#define LDG256(p, v) \
    asm volatile("ld.global.v8.f32 {%0,%1,%2,%3,%4,%5,%6,%7}, [%8];" \
        : "=f"(v[0]), "=f"(v[1]), "=f"(v[2]), "=f"(v[3]),            \
          "=f"(v[4]), "=f"(v[5]), "=f"(v[6]), "=f"(v[7])             \
        : "l"(p))

#define STG256(p, v) \
    asm volatile("st.global.v8.f32 [%0], {%1,%2,%3,%4,%5,%6,%7,%8};" \
        :: "l"(p),                                                    \
           "f"(v[0]), "f"(v[1]), "f"(v[2]), "f"(v[3]),               \
           "f"(v[4]), "f"(v[5]), "f"(v[6]), "f"(v[7])                \
        : "memory")

__global__ void __launch_bounds__(THREADS)
suffix_max_kernel(const float* __restrict__ in, float* __restrict__ out) {
    const int lane = threadIdx.x & 31;
    const int wrow = (blockIdx.x * (THREADS / 32)) + (threadIdx.x >> 5); // global row
    const unsigned row_off = (unsigned)wrow * ROW_LEN;

    const float* __restrict__ rin  = in  + row_off;
    float* __restrict__       rout = out + row_off;

    // ---- load 8 chunks of 8 floats: chunk index c = k*32 + lane ----
    float v[8][8];
    #pragma unroll
    for (int k = 0; k < 8; ++k)
        LDG256(rin + (unsigned)(k * 32 + lane) * 8u, v[k]);

    // ---- intra-chunk suffix max (8 independent chains) ----
    #pragma unroll
    for (int k = 0; k < 8; ++k) {
        v[k][6] = fmaxf(v[k][6], v[k][7]);
        v[k][5] = fmaxf(v[k][5], v[k][6]);
        v[k][4] = fmaxf(v[k][4], v[k][5]);
        v[k][3] = fmaxf(v[k][3], v[k][4]);
        v[k][2] = fmaxf(v[k][2], v[k][3]);
        v[k][1] = fmaxf(v[k][1], v[k][2]);
        v[k][0] = fmaxf(v[k][0], v[k][1]);
    }

    // ---- per-group warp inclusive suffix scans (8 interleaved chains) ----
    float i8[8];
    #pragma unroll
    for (int k = 0; k < 8; ++k) i8[k] = v[k][0];

    #pragma unroll
    for (int off = 1; off < 32; off <<= 1) {
        #pragma unroll
        for (int k = 0; k < 8; ++k)
            i8[k] = fmaxf(i8[k], __shfl_down_sync(0xffffffffu, i8[k], off));
    }

    // exclusive within group (lanes strictly right); lane 31 has none
    float e8[8];
    #pragma unroll
    for (int k = 0; k < 8; ++k) {
        e8[k] = __shfl_down_sync(0xffffffffu, i8[k], 1);
        if (lane == 31) e8[k] = NEG_INF;
    }

    // group totals (lane 0 of inclusive scan == group max), broadcast
    float T[8];
    #pragma unroll
    for (int k = 0; k < 8; ++k)
        T[k] = __shfl_sync(0xffffffffu, i8[k], 0);

    // suffix over group totals: S[k] = max(T[k+1..7])
    float S[8];
    S[7] = NEG_INF;
    S[6] = T[7];
    S[5] = fmaxf(T[6], S[6]);
    S[4] = fmaxf(T[5], S[5]);
    S[3] = fmaxf(T[4], S[4]);
    S[2] = fmaxf(T[3], S[3]);
    S[1] = fmaxf(T[2], S[2]);
    S[0] = fmaxf(T[1], S[1]);

    // ---- apply carries and store ----
    #pragma unroll
    for (int k = 0; k < 8; ++k) {
        const float c = fmaxf(e8[k], S[k]);
        #pragma unroll
        for (int j = 0; j < 8; ++j) v[k][j] = fmaxf(v[k][j], c);
        STG256(rout + (unsigned)(k * 32 + lane) * 8u, v[k]);
    }
}

extern "C" void kernel_launch(void* const* d_in, const int* in_sizes, int n_in,
                              void* d_out, int out_size) {
    const float* x = (const float*)d_in[0];
    float* out = (float*)d_out;
    const int n_rows = out_size / ROW_LEN;            // 16384
    const int n_blocks = n_rows / (THREADS / 32);     // 4096
    suffix_max_kernel<<<n_blocks, THREADS>>>(x, out);
}

// round 14
// speedup vs baseline: 1.0074x; 1.0074x over previous
#include <cuda_runtime.h>
#include <cstdint>

// Suffix (reverse cumulative) max along last dim.
// (8, 1, 2048, 2048) fp32 -> 16384 rows x 2048 cols.
// R14: TWO WARPS PER ROW (half-row per warp, 32 floats/lane, 4x LDG.256)
// -> ~52 regs/thread, ~2x occupancy vs R7. One smem float + one barrier
// couples the row halves. 256-thread CTAs = 4 rows/CTA.

#define ROW_LEN 2048
#define HALF    1024
#define THREADS 256           // 8 warps = 4 rows per CTA
#define NEG_INF __int_as_float(0xff800000)

#define LDG256(p, v) \
    asm volatile("ld.global.v8.f32 {%0,%1,%2,%3,%4,%5,%6,%7}, [%8];" \
        : "=f"(v[0]), "=f"(v[1]), "=f"(v[2]), "=f"(v[3]),            \
          "=f"(v[4]), "=f"(v[5]), "=f"(v[6]), "=f"(v[7])             \
        : "l"(p))

#define STG256(p, v) \
    asm volatile("st.global.v8.f32 [%0], {%1,%2,%3,%4,%5,%6,%7,%8};" \
        :: "l"(p),                                                    \
           "f"(v[0]), "f"(v[1]), "f"(v[2]), "f"(v[3]),               \
           "f"(v[4]), "f"(v[5]), "f"(v[6]), "f"(v[7])                \
        : "memory")

__global__ void __launch_bounds__(THREADS)
suffix_max_kernel(const float* __restrict__ in, float* __restrict__ out) {
    const int lane = threadIdx.x & 31;
    const int warp = threadIdx.x >> 5;       // 0..7
    const int lrow = warp >> 1;               // local row 0..3
    const int half = warp & 1;                // 0 = left half, 1 = right half

    const unsigned row_off  = (blockIdx.x * 4u + (unsigned)lrow) * ROW_LEN;
    const unsigned half_off = row_off + (unsigned)half * HALF;

    const float* __restrict__ rin  = in  + half_off;
    float* __restrict__       rout = out + half_off;

    __shared__ float hi_tot[4];               // right-half max per local row

    // ---- load 4 chunks of 8 floats: chunk c = k*32 + lane (within half) ----
    float v[4][8];
    #pragma unroll
    for (int k = 0; k < 4; ++k)
        LDG256(rin + (unsigned)(k * 32 + lane) * 8u, v[k]);

    // ---- intra-chunk suffix max (4 independent chains) ----
    #pragma unroll
    for (int k = 0; k < 4; ++k) {
        v[k][6] = fmaxf(v[k][6], v[k][7]);
        v[k][5] = fmaxf(v[k][5], v[k][6]);
        v[k][4] = fmaxf(v[k][4], v[k][5]);
        v[k][3] = fmaxf(v[k][3], v[k][4]);
        v[k][2] = fmaxf(v[k][2], v[k][3]);
        v[k][1] = fmaxf(v[k][1], v[k][2]);
        v[k][0] = fmaxf(v[k][0], v[k][1]);
    }

    // ---- per-group warp inclusive suffix scans (4 interleaved chains) ----
    float i4[4];
    #pragma unroll
    for (int k = 0; k < 4; ++k) i4[k] = v[k][0];

    #pragma unroll
    for (int off = 1; off < 32; off <<= 1) {
        #pragma unroll
        for (int k = 0; k < 4; ++k)
            i4[k] = fmaxf(i4[k], __shfl_down_sync(0xffffffffu, i4[k], off));
    }

    // exclusive within group
    float e4[4];
    #pragma unroll
    for (int k = 0; k < 4; ++k) {
        e4[k] = __shfl_down_sync(0xffffffffu, i4[k], 1);
        if (lane == 31) e4[k] = NEG_INF;
    }

    // group totals (broadcast lane 0 of inclusive scan)
    float T0 = __shfl_sync(0xffffffffu, i4[0], 0);
    float T1 = __shfl_sync(0xffffffffu, i4[1], 0);
    float T2 = __shfl_sync(0xffffffffu, i4[2], 0);
    float T3 = __shfl_sync(0xffffffffu, i4[3], 0);

    // publish right-half total; left half reads it after barrier
    if (half == 1 && lane == 0)
        hi_tot[lrow] = fmaxf(fmaxf(T0, T1), fmaxf(T2, T3));
    __syncthreads();

    // cross-half carry: left half sees the whole right half to its right
    const float cross = (half == 0) ? hi_tot[lrow] : NEG_INF;

    // suffix over group totals within the half: S[k] = max(T[k+1..3], cross)
    float S3 = cross;
    float S2 = fmaxf(T3, S3);
    float S1 = fmaxf(T2, S2);
    float S0 = fmaxf(T1, S1);

    const float c0 = fmaxf(e4[0], S0);
    const float c1 = fmaxf(e4[1], S1);
    const float c2 = fmaxf(e4[2], S2);
    const float c3 = fmaxf(e4[3], S3);

    // ---- apply carries and store ----
    #pragma unroll
    for (int j = 0; j < 8; ++j) {
        v[0][j] = fmaxf(v[0][j], c0);
        v[1][j] = fmaxf(v[1][j], c1);
        v[2][j] = fmaxf(v[2][j], c2);
        v[3][j] = fmaxf(v[3][j], c3);
    }

    #pragma unroll
    for (int k = 0; k < 4; ++k)
        STG256(rout + (unsigned)(k * 32 + lane) * 8u, v[k]);
}

extern "C" void kernel_launch(void* const* d_in, const int* in_sizes, int n_in,
                              void* d_out, int out_size) {
    const float* x = (const float*)d_in[0];
    float* out = (float*)d_out;
    const int n_rows = out_size / ROW_LEN;   // 16384
    const int n_blocks = n_rows / 4;         // 4096
    suffix_max_kernel<<<n_blocks, THREADS>>>(x, out);
}